// round 14
// baseline (speedup 1.0000x reference)
#include <cuda_runtime.h>
#include <cuda_bf16.h>
#include <math.h>
#include <stdint.h>
#include <stddef.h>

#define NB 64
#define Hd 2048
#define G3 6144
#define TT 32
#define MELN 130
#define CHN 12
#define RHYN 3
#define NBHd (NB*Hd)
#define K16N 128
#define FRAGU32 (4*128*32*8)
#define BPKSZ 3145728
#define SST (128*32)
#define BSTG 73728          // 3 stages x 4 quarters x 2 k16 x 6 streams x 32 lanes x 16B
#define SMEM_DYN (BSTG + 36864)

// ---------------- device globals -------------------------------------------------
__device__ float g_h[2*NBHd], g_ha[2*NBHd], g_hb[2*NBHd];
__device__ float g_gic0[NB*G3], g_gi1z[NB*G3];
__device__ float g_gi1t[(size_t)TT*NB*G3];
__device__ float g_rlo[TT*NB*RHYN];
__device__ int g_ridx[(TT+1)*NB], g_midx[(TT+1)*NB];
__device__ int g_bar, g_rfl, g_mfl;
__device__ uint4 g_Bp0[BPKSZ], g_Bp1[BPKSZ], g_Bp2i[BPKSZ], g_Bp2h[BPKSZ];
__device__ uint32_t g_hfrag[2][FRAGU32], g_hafrag[2][FRAGU32], g_hbfrag[2][FRAGU32];

// ---------------- helpers ---------------------------------------------------------
__device__ __forceinline__ float sigm_f(float x){ return 1.0f/(1.0f+expf(-x)); }
__device__ __forceinline__ float tanh_f(float x){ return 1.0f-2.0f/(expf(2.0f*x)+1.0f); }

__device__ __forceinline__ uint32_t packbf2(float x, float y){
    __nv_bfloat162 v = __floats2bfloat162_rn(x, y);
    return *reinterpret_cast<uint32_t*>(&v);
}
__device__ __forceinline__ void split2(float x, float y, uint32_t& hi, uint32_t& lo){
    __nv_bfloat16 hx = __float2bfloat16(x), hy = __float2bfloat16(y);
    float rx = x - __bfloat162float(hx);
    float ry = y - __bfloat162float(hy);
    __nv_bfloat162 H; H.x = hx; H.y = hy;
    hi = *reinterpret_cast<uint32_t*>(&H);
    lo = packbf2(rx, ry);
}
__device__ __forceinline__ void mma16816(float* d, uint32_t a0, uint32_t a1,
                                         uint32_t a2, uint32_t a3,
                                         uint32_t b0, uint32_t b1){
    asm volatile(
        "mma.sync.aligned.m16n8k16.row.col.f32.bf16.bf16.f32 "
        "{%0,%1,%2,%3}, {%4,%5,%6,%7}, {%8,%9}, {%0,%1,%2,%3};"
        : "+f"(d[0]), "+f"(d[1]), "+f"(d[2]), "+f"(d[3])
        : "r"(a0), "r"(a1), "r"(a2), "r"(a3), "r"(b0), "r"(b1));
}
__device__ __forceinline__ void mma_step6(float acc[2][3][4], const uint4& ah,
                                          const uint4& al, const uint4 b[6]){
    mma16816(acc[0][0], ah.x,ah.y,ah.z,ah.w, b[0].x,b[0].y);
    mma16816(acc[0][1], ah.x,ah.y,ah.z,ah.w, b[2].x,b[2].y);
    mma16816(acc[0][2], ah.x,ah.y,ah.z,ah.w, b[4].x,b[4].y);
    mma16816(acc[1][0], ah.x,ah.y,ah.z,ah.w, b[1].x,b[1].y);
    mma16816(acc[1][1], ah.x,ah.y,ah.z,ah.w, b[3].x,b[3].y);
    mma16816(acc[1][2], ah.x,ah.y,ah.z,ah.w, b[5].x,b[5].y);
    mma16816(acc[0][0], ah.x,ah.y,ah.z,ah.w, b[0].z,b[0].w);
    mma16816(acc[0][1], ah.x,ah.y,ah.z,ah.w, b[2].z,b[2].w);
    mma16816(acc[0][2], ah.x,ah.y,ah.z,ah.w, b[4].z,b[4].w);
    mma16816(acc[1][0], ah.x,ah.y,ah.z,ah.w, b[1].z,b[1].w);
    mma16816(acc[1][1], ah.x,ah.y,ah.z,ah.w, b[3].z,b[3].w);
    mma16816(acc[1][2], ah.x,ah.y,ah.z,ah.w, b[5].z,b[5].w);
    mma16816(acc[0][0], al.x,al.y,al.z,al.w, b[0].x,b[0].y);
    mma16816(acc[0][1], al.x,al.y,al.z,al.w, b[2].x,b[2].y);
    mma16816(acc[0][2], al.x,al.y,al.z,al.w, b[4].x,b[4].y);
    mma16816(acc[1][0], al.x,al.y,al.z,al.w, b[1].x,b[1].y);
    mma16816(acc[1][1], al.x,al.y,al.z,al.w, b[3].x,b[3].y);
    mma16816(acc[1][2], al.x,al.y,al.z,al.w, b[5].x,b[5].y);
}

__device__ __forceinline__ void gbar(int& tgt){
    __threadfence();
    __syncthreads();
    if (threadIdx.x == 0){
        tgt += 128;
        atomicAdd(&g_bar, 1);
        int v;
        do {
            asm volatile("ld.acquire.gpu.global.b32 %0, [%1];" : "=r"(v) : "l"(&g_bar));
        } while (v < tgt);
    }
    __syncthreads();
}
__device__ __forceinline__ void spinflag(int* f, int target){
    int v;
    do {
        asm volatile("ld.acquire.gpu.global.b32 %0, [%1];" : "=r"(v) : "l"(f));
    } while (v < target);
}

// ---------------- init kernel -----------------------------------------------------
__global__ void k_init(){
    int i = threadIdx.x;
    if (i == 0){ g_bar = 0; g_rfl = 0; g_mfl = 0; }
    if (i < NB){ g_ridx[i] = RHYN-1; g_midx[i] = MELN-1; }
}

// ---------------- frag mapping (b, u0-even) ---------------------------------------
__device__ __forceinline__ void frag_write(uint32_t* __restrict__ Frag,
                                           int b, int u0, float h0, float h1)
{
    uint32_t hi, lo; split2(h0, h1, hi, lo);
    int mt = b >> 4, rw = b & 15, q = rw & 7, rs = rw >> 3;
    int k16 = u0 >> 4, kk = u0 & 15, tp = (kk & 7) >> 1;
    int r = ((kk >= 8) ? 2 : 0) + rs;
    uint32_t* fb = Frag + (((size_t)mt*128 + k16)*32 + q*4 + tp)*8;
    fb[r] = hi; fb[r + 4] = lo;
}

// ---------------- GEMM tile: cp.async 3-stage B pipeline --------------------------
__device__ __forceinline__ void b_issue(const uint4* __restrict__ Bpk, int jt,
                                        uint32_t sb, int i, int st)
{
    int tid = threadIdx.x;
#pragma unroll
    for (int j = 0; j < 3; j++){
        int idx = tid + j*512;
        int ll = idx & 31;
        int ss = (idx >> 5) % 6;
        int r = idx / 192;               // 0..7
        int p = r & 1, q = r >> 1;
        int k16g = q*32 + 2*i + p;
        const void* src = Bpk + ((size_t)(jt*6 + ss)*128 + k16g)*32 + ll;
        uint32_t dst = sb + (uint32_t)(((((st*4 + q)*2 + p)*6 + ss)*32 + ll)*16);
        asm volatile("cp.async.cg.shared.global [%0],[%1],16;" :: "r"(dst), "l"(src));
    }
    asm volatile("cp.async.commit_group;" ::: "memory");
}

__device__ __forceinline__ void gemm_acc(const uint4* __restrict__ Bpk,
                                         const uint32_t* __restrict__ Af,
                                         float acc[2][3][4],
                                         char* bsm, float* sred)
{
    __syncthreads();   // protect bsm/sred reuse from previous phase
    int tid = threadIdx.x, jt = blockIdx.x;
    int w = tid >> 5, l = tid & 31;
    int mt = w & 3, kh = w >> 2;
#pragma unroll
    for (int n = 0; n < 2; n++)
#pragma unroll
        for (int g = 0; g < 3; g++)
#pragma unroll
            for (int i = 0; i < 4; i++) acc[n][g][i] = 0.f;

    uint32_t sb = (uint32_t)__cvta_generic_to_shared(bsm);
    b_issue(Bpk, jt, sb, 0, 0);
    b_issue(Bpk, jt, sb, 1, 1);

    const uint4* ap4 = (const uint4*)(Af + (((size_t)mt*K16N + kh*32)*32 + l)*8);
    uint4 A0h = __ldcg(ap4), A0l = __ldcg(ap4+1);
    uint4 A1h = __ldcg(ap4+64), A1l = __ldcg(ap4+65);

#pragma unroll 1
    for (int i = 0; i < 16; i++){
        if (i < 15) asm volatile("cp.async.wait_group 1;" ::: "memory");
        else        asm volatile("cp.async.wait_group 0;" ::: "memory");
        __syncthreads();
        if (i < 14) b_issue(Bpk, jt, sb, i + 2, (i + 2) % 3);

        int st = i % 3;
        const uint4* bs0 = (const uint4*)(bsm + (size_t)(((st*4 + kh)*2 + 0)*6)*32*16) + l;
        const uint4* bs1 = (const uint4*)(bsm + (size_t)(((st*4 + kh)*2 + 1)*6)*32*16) + l;
        uint4 B0[6], B1[6];
#pragma unroll
        for (int s = 0; s < 6; s++){ B0[s] = bs0[s*32]; B1[s] = bs1[s*32]; }

        int adv = (i < 15) ? 128 : 0;
        uint4 nA0h = __ldcg(ap4 + adv), nA0l = __ldcg(ap4 + adv + 1);
        uint4 nA1h = __ldcg(ap4 + adv + 64), nA1l = __ldcg(ap4 + adv + 65);

        mma_step6(acc, A0h, A0l, B0);
        mma_step6(acc, A1h, A1l, B1);

        A0h = nA0h; A0l = nA0l; A1h = nA1h; A1l = nA1l;
        ap4 += adv;
    }

    if (kh){
#pragma unroll
        for (int n = 0; n < 2; n++)
#pragma unroll
            for (int g = 0; g < 3; g++)
#pragma unroll
                for (int i = 0; i < 4; i++)
                    sred[(((kh-1)*4 + mt)*32 + l)*24 + (n*3+g)*4 + i] = acc[n][g][i];
    }
    __syncthreads();
    if (!kh){
#pragma unroll
        for (int s = 0; s < 3; s++)
#pragma unroll
            for (int n = 0; n < 2; n++)
#pragma unroll
                for (int g = 0; g < 3; g++)
#pragma unroll
                    for (int i = 0; i < 4; i++)
                        acc[n][g][i] += sred[((s*4 + mt)*32 + l)*24 + (n*3+g)*4 + i];
    }
}

// ---------------- epilogues (unchanged numerics) ----------------------------------
__device__ __forceinline__ void epiA(const float acc[2][3][4],
    const float* __restrict__ bias, const float* __restrict__ gi,
    const float* __restrict__ Woh, int ldw, const int* __restrict__ idx,
    const float* __restrict__ Hfp, float* __restrict__ outH,
    uint32_t* __restrict__ Frag)
{
    int tid = threadIdx.x, jt = blockIdx.x;
    int mt = tid >> 5, l = tid & 31;
    int q = l >> 2, tp = l & 3;
    int m0 = mt*16 + q, m1 = m0 + 8;
    int ix0 = __ldcg(idx + m0), ix1 = __ldcg(idx + m1);
    int lp = q*4 + tp;
    uint32_t* fb = Frag + (((size_t)mt*K16N + jt)*32 + lp)*8;
#pragma unroll
    for (int nh = 0; nh < 2; nh++){
        int c0 = jt*16 + nh*8 + 2*tp, c1 = c0 + 1;
        float br = __ldg(bias+c0), brX = __ldg(bias+c1);
        float bz = __ldg(bias+Hd+c0), bzX = __ldg(bias+Hd+c1);
        float bn = __ldg(bias+2*Hd+c0), bnX = __ldg(bias+2*Hd+c1);
        float hout[4];
#pragma unroll
        for (int v = 0; v < 4; v++){
            int b = (v & 2) ? m1 : m0;
            int c = (v & 1) ? c1 : c0;
            int ix = (v & 2) ? ix1 : ix0;
            float gir = __ldcg(gi + (size_t)b*G3 + c) + __ldg(Woh + (size_t)c*ldw + ix);
            float giz = __ldcg(gi + (size_t)b*G3 + Hd + c) + __ldg(Woh + (size_t)(Hd+c)*ldw + ix);
            float gin = __ldcg(gi + (size_t)b*G3 + 2*Hd + c) + __ldg(Woh + (size_t)(2*Hd+c)*ldw + ix);
            float ghr = acc[nh][0][v] + ((v & 1) ? brX : br);
            float ghz = acc[nh][1][v] + ((v & 1) ? bzX : bz);
            float ghn = acc[nh][2][v] + ((v & 1) ? bnX : bn);
            float r = sigm_f(gir + ghr);
            float u = sigm_f(giz + ghz);
            float n = tanh_f(gin + r*ghn);
            float hp = __ldcg(Hfp + (size_t)b*Hd + c);
            hout[v] = (1.f - u)*n + u*hp;
            outH[(size_t)b*Hd + c] = hout[v];
        }
        uint32_t hi0, lo0, hi1, lo1;
        split2(hout[0], hout[1], hi0, lo0);
        split2(hout[2], hout[3], hi1, lo1);
        fb[nh*2 + 0] = hi0; fb[nh*2 + 1] = hi1;
        fb[4 + nh*2 + 0] = lo0; fb[4 + nh*2 + 1] = lo1;
    }
}

__device__ __forceinline__ void epi2(const float acc[2][3][4], const float gh2[2][3][4],
    const float* __restrict__ bi, const float* __restrict__ bh,
    const float* __restrict__ Hfp, float* __restrict__ outH,
    uint32_t* __restrict__ Frag)
{
    int tid = threadIdx.x, jt = blockIdx.x;
    int mt = tid >> 5, l = tid & 31;
    int q = l >> 2, tp = l & 3;
    int m0 = mt*16 + q, m1 = m0 + 8;
    int lp = q*4 + tp;
    uint32_t* fb = Frag + (((size_t)mt*K16N + jt)*32 + lp)*8;
#pragma unroll
    for (int nh = 0; nh < 2; nh++){
        int c0 = jt*16 + nh*8 + 2*tp, c1 = c0 + 1;
        float hout[4];
#pragma unroll
        for (int v = 0; v < 4; v++){
            int b = (v & 2) ? m1 : m0;
            int c = (v & 1) ? c1 : c0;
            float gir = acc[nh][0][v] + __ldg(bi + c);
            float giz = acc[nh][1][v] + __ldg(bi + Hd + c);
            float gin = acc[nh][2][v] + __ldg(bi + 2*Hd + c);
            float ghr = gh2[nh][0][v] + __ldg(bh + c);
            float ghz = gh2[nh][1][v] + __ldg(bh + Hd + c);
            float ghn = gh2[nh][2][v] + __ldg(bh + 2*Hd + c);
            float r = sigm_f(gir + ghr);
            float u = sigm_f(giz + ghz);
            float n = tanh_f(gin + r*ghn);
            float hp = __ldcg(Hfp + (size_t)b*Hd + c);
            hout[v] = (1.f - u)*n + u*hp;
            outH[(size_t)b*Hd + c] = hout[v];
        }
        uint32_t hi0, lo0, hi1, lo1;
        split2(hout[0], hout[1], hi0, lo0);
        split2(hout[2], hout[3], hi1, lo1);
        fb[nh*2 + 0] = hi0; fb[nh*2 + 1] = hi1;
        fb[4 + nh*2 + 0] = lo0; fb[4 + nh*2 + 1] = lo1;
    }
}

// ---------------- logits bodies (flag-producing) ----------------------------------
__device__ __forceinline__ void rhy_body(const float* __restrict__ Hn,
    const float* __restrict__ wo0, const float* __restrict__ bo0,
    float* __restrict__ rlo, int* __restrict__ ridx, float* sm)
{
    int b = blockIdx.x, tid = threadIdx.x;
    if (tid < 384){
        int g = tid >> 7, s = tid & 127;
        float p = 0.f;
        for (int k = s; k < Hd; k += 128)
            p += __ldcg(Hn + (size_t)b*Hd + k) * __ldg(wo0 + (size_t)g*Hd + k);
        sm[tid] = p;
    }
    __syncthreads();
    for (int off = 64; off > 0; off >>= 1){
        if (tid < 384 && (tid & 127) < off) sm[tid] += sm[tid + off];
        __syncthreads();
    }
    if (tid == 0){
        float l0 = sm[0] + __ldg(bo0+0), l1 = sm[128] + __ldg(bo0+1), l2 = sm[256] + __ldg(bo0+2);
        float m = fmaxf(l0, fmaxf(l1, l2));
        float z = m + logf(expf(l0-m) + expf(l1-m) + expf(l2-m));
        rlo[b*3+0] = l0 - z; rlo[b*3+1] = l1 - z; rlo[b*3+2] = l2 - z;
        int ix = 0; float bv = l0;
        if (l1 > bv){ bv = l1; ix = 1; }
        if (l2 > bv){ bv = l2; ix = 2; }
        ridx[b] = ix;
        __threadfence();
        atomicAdd(&g_rfl, 1);
    }
    __syncthreads();
}

__device__ __forceinline__ void mel_body(const float* __restrict__ Hn,
    const float* __restrict__ wo1, const float* __restrict__ bo1,
    float* __restrict__ outmel, int t, int* __restrict__ midx, float* sm)
{
    float* hs = sm;
    float* ls = sm + 2048;
    float* red = sm + 2208;
    int b = blockIdx.x, tid = threadIdx.x;
    for (int k = tid; k < Hd; k += 512) hs[k] = __ldcg(Hn + (size_t)b*Hd + k);
    __syncthreads();
    int w = tid >> 5, l = tid & 31;
    const float4* h4 = (const float4*)hs;
    for (int r = w; r < MELN; r += 16){
        const float4* w4 = (const float4*)(wo1 + (size_t)r*Hd);
        float s = 0.f;
        for (int c = l; c < Hd/4; c += 32){
            float4 a = h4[c], q = __ldg(w4 + c);
            s += a.x*q.x + a.y*q.y + a.z*q.z + a.w*q.w;
        }
#pragma unroll
        for (int off = 16; off > 0; off >>= 1) s += __shfl_xor_sync(0xffffffffu, s, off);
        if (l == 0) ls[r] = s + __ldg(bo1 + r);
    }
    __syncthreads();
    red[tid] = (tid < MELN) ? ls[tid] : -3.4e38f;
    __syncthreads();
    for (int off = 256; off > 0; off >>= 1){
        if (tid < off) red[tid] = fmaxf(red[tid], red[tid + off]);
        __syncthreads();
    }
    float m = red[0];
    __syncthreads();
    red[tid] = (tid < MELN) ? expf(ls[tid] - m) : 0.f;
    __syncthreads();
    for (int off = 256; off > 0; off >>= 1){
        if (tid < off) red[tid] += red[tid + off];
        __syncthreads();
    }
    float z = m + logf(red[0]);
    if (tid < MELN)
        outmel[((size_t)b*TT + t)*MELN + tid] = ls[tid] - z;
    if (tid == 0){
        int ix = 0; float bv = ls[0];
        for (int c = 1; c < MELN; c++) if (ls[c] > bv){ bv = ls[c]; ix = c; }
        midx[b] = ix;
        __threadfence();
        atomicAdd(&g_mfl, 1);
    }
    __syncthreads();
}

__device__ __forceinline__ void gi1t_body(const float* __restrict__ cond,
                                          const float* __restrict__ w_ih1)
{
    int id = blockIdx.x*512 + threadIdx.x;
#pragma unroll 1
    for (int r = 0; r < 3; r++){
        int id2 = id + r*65536;
        int t = id2 / G3;
        int n = id2 - t*G3;
        float wr[RHYN], wc[CHN];
#pragma unroll
        for (int j = 0; j < RHYN; j++) wr[j] = __ldg(w_ih1 + (size_t)n*273 + MELN + j);
#pragma unroll
        for (int j = 0; j < CHN; j++)
            wc[j] = __ldg(w_ih1 + (size_t)n*273 + MELN + RHYN + 128 + j);
#pragma unroll 1
        for (int b = 0; b < NB; b++){
            float s = g_gi1z[(size_t)b*G3 + n];
            const float* rl = g_rlo + (t*NB + b)*RHYN;
            s += __ldcg(rl)*wr[0] + __ldcg(rl+1)*wr[1] + __ldcg(rl+2)*wr[2];
            const float* c = cond + ((size_t)b*TT + t)*CHN;
#pragma unroll
            for (int j = 0; j < CHN; j++) s += __ldg(c + j)*wc[j];
            g_gi1t[((size_t)t*NB + b)*G3 + n] = s;
        }
    }
}

// ---------------- persistent main kernel ------------------------------------------
__global__ __launch_bounds__(512, 1) void k_main(
    const float* __restrict__ w_ih0, const float* __restrict__ b_hh0,
    const float* __restrict__ w_ih1, const float* __restrict__ b_hh1,
    const float* __restrict__ b_ih2, const float* __restrict__ b_hh2,
    const float* __restrict__ wo0, const float* __restrict__ bo0,
    const float* __restrict__ wo1, const float* __restrict__ bo1,
    const float* __restrict__ cond, float* __restrict__ out,
    const float* __restrict__ z1, const float* __restrict__ z2,
    const float* __restrict__ wi0, const float* __restrict__ bi0,
    const float* __restrict__ wi1, const float* __restrict__ bi1,
    const float* __restrict__ b_ih0, const float* __restrict__ b_ih1,
    const float* __restrict__ w_hh0, const float* __restrict__ w_hh1,
    const float* __restrict__ w_ih2, const float* __restrict__ w_hh2)
{
    extern __shared__ __align__(128) char smdyn[];
    char* bsm = smdyn;
    float* pool = (float*)(smdyn + BSTG);
    int tgt = 0;
    int tid = threadIdx.x, bid = blockIdx.x;
    float acc[2][3][4];

    // ================= phase 0: precompute (mv jobs + weight pack) =================
    {
        const float *zsrc, *W, *bias;
        int ldw, off, isH, nbase;
        float* dsth = 0; uint32_t* dstf = 0; float* dstg = 0;
        if (bid < 16){ zsrc=z2; W=wi0; bias=bi0; ldw=128; off=0; isH=1;
                       dsth=g_h; dstf=g_hfrag[0]; nbase=bid*128; }
        else if (bid < 32){ zsrc=z1; W=wi1; bias=bi1; ldw=128; off=0; isH=1;
                       dsth=g_ha; dstf=g_hafrag[0]; nbase=(bid-16)*128; }
        else if (bid < 80){ zsrc=z2; W=w_ih0; bias=b_ih0; ldw=131; off=RHYN; isH=0;
                       dstg=g_gic0; nbase=(bid-32)*128; }
        else { zsrc=z1; W=w_ih1; bias=b_ih1; ldw=273; off=MELN+RHYN; isH=0;
                       dstg=g_gi1z; nbase=(bid-80)*128; }
        for (int i = tid; i < 8192; i += 512)
            pool[(i & 127)*64 + (i >> 7)] = __ldg(zsrc + (i >> 7)*128 + (i & 127));
        __syncthreads();
        int np = tid >> 3, bg = tid & 7;
        int n0 = nbase + np*2;
        const float* w0 = W + (size_t)n0*ldw + off;
        const float* w1 = w0 + ldw;
        float a0[8], a1[8];
#pragma unroll
        for (int j = 0; j < 8; j++){ a0[j] = 0.f; a1[j] = 0.f; }
        for (int k = 0; k < 128; k++){
            float u = __ldg(w0 + k), v = __ldg(w1 + k);
            const float* zp = pool + k*64 + bg*8;
#pragma unroll
            for (int j = 0; j < 8; j++){
                float xv = zp[j];
                a0[j] += xv*u; a1[j] += xv*v;
            }
        }
        float b0v = __ldg(bias + n0), b1v = __ldg(bias + n0 + 1);
#pragma unroll
        for (int j = 0; j < 8; j++){
            int b = bg*8 + j;
            float v0 = a0[j] + b0v, v1 = a1[j] + b1v;
            if (isH){
                v0 = tanh_f(v0); v1 = tanh_f(v1);
                *(float2*)&dsth[(size_t)b*Hd + n0] = make_float2(v0, v1);
                frag_write(dstf, b, n0, v0, v1);
            } else {
                *(float2*)&dstg[(size_t)b*G3 + n0] = make_float2(v0, v1);
            }
        }
        __syncthreads();
        const float* Ws[4] = { w_hh0, w_hh1, w_ih2, w_hh2 };
        uint4* Os[4] = { g_Bp0, g_Bp1, g_Bp2i, g_Bp2h };
#pragma unroll 1
        for (int mat = 0; mat < 4; mat++){
            const float* W4 = Ws[mat];
            uint4* o4 = Os[mat];
#pragma unroll 1
            for (int it = 0; it < 48; it++){
                int id = (bid*512 + tid) + it*65536;
                int l = id & 31, nt = id >> 12;
                int P = nt*8 + (l >> 2);
                int jt = P/48, rem = P%48, g = rem >> 4, c = rem & 15;
                int k16 = (id >> 5) & 127;
                const float* wr = W4 + (size_t)(g*Hd + jt*16 + c)*Hd + k16*16 + 2*(l&3);
                uint4 vv;
                split2(__ldg(wr), __ldg(wr+1), vv.x, vv.z);
                split2(__ldg(wr+8), __ldg(wr+9), vv.y, vv.w);
                o4[id] = vv;
            }
        }
        gbar(tgt);
    }

    // ================= rhythm phase (1 barrier/step) ===============================
#pragma unroll 1
    for (int t = 0; t < TT; t++){
        int cu = t & 1, nx = cu ^ 1;
        if (bid < NB && t > 0)
            rhy_body(g_h + (size_t)cu*NBHd, wo0, bo0,
                     g_rlo + (t-1)*NB*RHYN, g_ridx + t*NB, pool);
        gemm_acc(g_Bp0, g_hfrag[cu], acc, bsm, pool);
        if (tid == 0) spinflag(&g_rfl, 64*t);
        __syncthreads();
        if (tid < 128)
            epiA(acc, b_hh0, g_gic0, w_ih0, 131, g_ridx + t*NB,
                 g_h + (size_t)cu*NBHd, g_h + (size_t)nx*NBHd, g_hfrag[nx]);
        gbar(tgt);
    }
    if (bid < NB)
        rhy_body(g_h + (size_t)0*NBHd, wo0, bo0,
                 g_rlo + 31*NB*RHYN, g_ridx + 32*NB, pool);
    gbar(tgt);
    gi1t_body(cond, w_ih1);
    gbar(tgt);

    // ================= melody phase (2 barriers/step) ==============================
#pragma unroll 1
    for (int t = 0; t < TT; t++){
        int cu = t & 1, nx = cu ^ 1;
        if (bid < NB && t > 0)
            mel_body(g_hb + (size_t)cu*NBHd, wo1, bo1, out, t-1,
                     g_midx + t*NB, pool);
        gemm_acc(g_Bp1, g_hafrag[cu], acc, bsm, pool);
        if (tid == 0) spinflag(&g_mfl, 64*t);
        __syncthreads();
        if (tid < 128)
            epiA(acc, b_hh1, g_gi1t + (size_t)t*NB*G3, w_ih1, 273, g_midx + t*NB,
                 g_ha + (size_t)cu*NBHd, g_ha + (size_t)nx*NBHd, g_hafrag[nx]);
        gbar(tgt);
        const uint32_t* fbin = (t == 0) ? g_hafrag[1] : g_hbfrag[cu];
        const float* hbprev = (t == 0) ? (g_ha + (size_t)NBHd) : (g_hb + (size_t)cu*NBHd);
        gemm_acc(g_Bp2h, fbin, acc, bsm, pool);
        float gh2[2][3][4];
        if (tid < 128){
#pragma unroll
            for (int n = 0; n < 2; n++)
#pragma unroll
                for (int g = 0; g < 3; g++)
#pragma unroll
                    for (int i = 0; i < 4; i++) gh2[n][g][i] = acc[n][g][i];
        }
        gemm_acc(g_Bp2i, g_hafrag[nx], acc, bsm, pool);
        if (tid < 128)
            epi2(acc, gh2, b_ih2, b_hh2, hbprev,
                 g_hb + (size_t)nx*NBHd, g_hbfrag[nx]);
        gbar(tgt);
    }
    if (bid < NB)
        mel_body(g_hb + (size_t)0*NBHd, wo1, bo1, out, 31, g_midx + 32*NB, pool);
}

// ---------------- host driver ------------------------------------------------------
extern "C" void kernel_launch(void* const* d_in, const int* in_sizes, int n_in,
                              void* d_out, int out_size)
{
    const float* z1    = (const float*)d_in[0];
    const float* z2    = (const float*)d_in[1];
    const float* cond  = (const float*)d_in[2];
    const float* w_ih0 = (const float*)d_in[3];
    const float* w_hh0 = (const float*)d_in[4];
    const float* b_ih0 = (const float*)d_in[5];
    const float* b_hh0 = (const float*)d_in[6];
    const float* w_ih1 = (const float*)d_in[7];
    const float* w_hh1 = (const float*)d_in[8];
    const float* b_ih1 = (const float*)d_in[9];
    const float* b_hh1 = (const float*)d_in[10];
    const float* w_ih2 = (const float*)d_in[11];
    const float* w_hh2 = (const float*)d_in[12];
    const float* b_ih2 = (const float*)d_in[13];
    const float* b_hh2 = (const float*)d_in[14];
    const float* wi0   = (const float*)d_in[15];
    const float* bi0   = (const float*)d_in[16];
    const float* wo0   = (const float*)d_in[17];
    const float* bo0   = (const float*)d_in[18];
    const float* wi1   = (const float*)d_in[19];
    const float* bi1   = (const float*)d_in[20];
    const float* wo1   = (const float*)d_in[21];
    const float* bo1   = (const float*)d_in[22];
    float* out = (float*)d_out;

    cudaFuncSetAttribute(k_main, cudaFuncAttributeMaxDynamicSharedMemorySize, SMEM_DYN);

    k_init<<<1, 64>>>();
    k_main<<<128, 512, SMEM_DYN>>>(w_ih0, b_hh0, w_ih1, b_hh1, b_ih2, b_hh2,
                                   wo0, bo0, wo1, bo1, cond, out,
                                   z1, z2, wi0, bi0, wi1, bi1, b_ih0, b_ih1,
                                   w_hh0, w_hh1, w_ih2, w_hh2);
}

// round 15
// speedup vs baseline: 1.2339x; 1.2339x over previous
#include <cuda_runtime.h>
#include <cuda_bf16.h>
#include <math.h>
#include <stdint.h>
#include <stddef.h>

#define NB 64
#define Hd 2048
#define G3 6144
#define TT 32
#define MELN 130
#define CHN 12
#define RHYN 3
#define NBHd (NB*Hd)
#define K16N 128
#define FRAGU32 (4*128*32*8)
#define BPKSZ 3145728
#define SST (128*32)

// ---------------- device globals -------------------------------------------------
__device__ float g_h[2*NBHd], g_ha[2*NBHd], g_hb[2*NBHd];
__device__ float g_gic0[NB*G3], g_gi1z[NB*G3];
__device__ float g_gi1t[(size_t)TT*NB*G3];
__device__ float g_rlo[TT*NB*RHYN];
__device__ int g_ridx[(TT+1)*NB], g_midx[(TT+1)*NB];
__device__ int g_bar, g_rfl, g_mfl;
__device__ uint4 g_Bp0[BPKSZ], g_Bp1[BPKSZ], g_Bp2i[BPKSZ], g_Bp2h[BPKSZ];
__device__ uint32_t g_hfrag[2][FRAGU32], g_hafrag[2][FRAGU32], g_hbfrag[2][FRAGU32];

// ---------------- helpers ---------------------------------------------------------
__device__ __forceinline__ float sigm_f(float x){ return 1.0f/(1.0f+expf(-x)); }
__device__ __forceinline__ float tanh_f(float x){ return 1.0f-2.0f/(expf(2.0f*x)+1.0f); }

__device__ __forceinline__ uint32_t packbf2(float x, float y){
    __nv_bfloat162 v = __floats2bfloat162_rn(x, y);
    return *reinterpret_cast<uint32_t*>(&v);
}
__device__ __forceinline__ void split2(float x, float y, uint32_t& hi, uint32_t& lo){
    __nv_bfloat16 hx = __float2bfloat16(x), hy = __float2bfloat16(y);
    float rx = x - __bfloat162float(hx);
    float ry = y - __bfloat162float(hy);
    __nv_bfloat162 H; H.x = hx; H.y = hy;
    hi = *reinterpret_cast<uint32_t*>(&H);
    lo = packbf2(rx, ry);
}
__device__ __forceinline__ void mma16816(float* d, uint32_t a0, uint32_t a1,
                                         uint32_t a2, uint32_t a3,
                                         uint32_t b0, uint32_t b1){
    asm volatile(
        "mma.sync.aligned.m16n8k16.row.col.f32.bf16.bf16.f32 "
        "{%0,%1,%2,%3}, {%4,%5,%6,%7}, {%8,%9}, {%0,%1,%2,%3};"
        : "+f"(d[0]), "+f"(d[1]), "+f"(d[2]), "+f"(d[3])
        : "r"(a0), "r"(a1), "r"(a2), "r"(a3), "r"(b0), "r"(b1));
}
__device__ __forceinline__ void mma_step6(float acc[2][3][4], const uint4& ah,
                                          const uint4& al, const uint4 b[6]){
    mma16816(acc[0][0], ah.x,ah.y,ah.z,ah.w, b[0].x,b[0].y);
    mma16816(acc[0][1], ah.x,ah.y,ah.z,ah.w, b[2].x,b[2].y);
    mma16816(acc[0][2], ah.x,ah.y,ah.z,ah.w, b[4].x,b[4].y);
    mma16816(acc[1][0], ah.x,ah.y,ah.z,ah.w, b[1].x,b[1].y);
    mma16816(acc[1][1], ah.x,ah.y,ah.z,ah.w, b[3].x,b[3].y);
    mma16816(acc[1][2], ah.x,ah.y,ah.z,ah.w, b[5].x,b[5].y);
    mma16816(acc[0][0], ah.x,ah.y,ah.z,ah.w, b[0].z,b[0].w);
    mma16816(acc[0][1], ah.x,ah.y,ah.z,ah.w, b[2].z,b[2].w);
    mma16816(acc[0][2], ah.x,ah.y,ah.z,ah.w, b[4].z,b[4].w);
    mma16816(acc[1][0], ah.x,ah.y,ah.z,ah.w, b[1].z,b[1].w);
    mma16816(acc[1][1], ah.x,ah.y,ah.z,ah.w, b[3].z,b[3].w);
    mma16816(acc[1][2], ah.x,ah.y,ah.z,ah.w, b[5].z,b[5].w);
    mma16816(acc[0][0], al.x,al.y,al.z,al.w, b[0].x,b[0].y);
    mma16816(acc[0][1], al.x,al.y,al.z,al.w, b[2].x,b[2].y);
    mma16816(acc[0][2], al.x,al.y,al.z,al.w, b[4].x,b[4].y);
    mma16816(acc[1][0], al.x,al.y,al.z,al.w, b[1].x,b[1].y);
    mma16816(acc[1][1], al.x,al.y,al.z,al.w, b[3].x,b[3].y);
    mma16816(acc[1][2], al.x,al.y,al.z,al.w, b[5].x,b[5].y);
}

__device__ __forceinline__ void gbar(int& tgt){
    __threadfence();
    __syncthreads();
    if (threadIdx.x == 0){
        tgt += 128;
        atomicAdd(&g_bar, 1);
        int v;
        do {
            asm volatile("ld.acquire.gpu.global.b32 %0, [%1];" : "=r"(v) : "l"(&g_bar));
        } while (v < tgt);
    }
    __syncthreads();
}
__device__ __forceinline__ void spinflag(int* f, int target){
    int v;
    do {
        asm volatile("ld.acquire.gpu.global.b32 %0, [%1];" : "=r"(v) : "l"(f));
    } while (v < target);
}

// ---------------- init kernel -----------------------------------------------------
__global__ void k_init(){
    int i = threadIdx.x;
    if (i == 0){ g_bar = 0; g_rfl = 0; g_mfl = 0; }
    if (i < NB){ g_ridx[i] = RHYN-1; g_midx[i] = MELN-1; }
}

// ---------------- frag mapping (b, u0-even) ---------------------------------------
__device__ __forceinline__ void frag_write(uint32_t* __restrict__ Frag,
                                           int b, int u0, float h0, float h1)
{
    uint32_t hi, lo; split2(h0, h1, hi, lo);
    int mt = b >> 4, rw = b & 15, q = rw & 7, rs = rw >> 3;
    int k16 = u0 >> 4, kk = u0 & 15, tp = (kk & 7) >> 1;
    int r = ((kk >= 8) ? 2 : 0) + rs;
    uint32_t* fb = Frag + (((size_t)mt*128 + k16)*32 + q*4 + tp)*8;
    fb[r] = hi; fb[r + 4] = lo;
}

// ---------------- GEMM tile (R13 + B L2-prefetch) ---------------------------------
__device__ __forceinline__ void gemm_acc(const uint4* __restrict__ Bpk,
                                         const uint32_t* __restrict__ Af,
                                         float acc[2][3][4], float* sred)
{
    __syncthreads();
    int tid = threadIdx.x, jt = blockIdx.x;
    int w = tid >> 5, l = tid & 31;
    int mt = w & 3, kh = w >> 2;
#pragma unroll
    for (int n = 0; n < 2; n++)
#pragma unroll
        for (int g = 0; g < 3; g++)
#pragma unroll
            for (int i = 0; i < 4; i++) acc[n][g][i] = 0.f;

    const uint4* bptr = Bpk + ((size_t)(jt*6)*K16N + kh*32)*32 + l;
    const uint4* ap4 = (const uint4*)(Af + (((size_t)mt*K16N + kh*32)*32 + l)*8);

    // prime L2 for the first ~8 k16 of each stream (mt spreads distinct offsets)
#pragma unroll
    for (int s = 0; s < 6; s++)
        asm volatile("prefetch.global.L2 [%0];" :: "l"(bptr + (size_t)s*SST + mt*64));

    uint4 A0h = __ldcg(ap4), A0l = __ldcg(ap4+1);
    uint4 A1h = __ldcg(ap4+64), A1l = __ldcg(ap4+65);
    uint4 B0[6], B1[6];
#pragma unroll
    for (int s = 0; s < 6; s++){
        B0[s] = __ldg(bptr + (size_t)s*SST);
        B1[s] = __ldg(bptr + (size_t)s*SST + 32);
    }
#pragma unroll 1
    for (int k16 = 0; k16 < 30; k16 += 2){
        // prefetch B 8 k16 ahead (256 uint4) so __ldg below hits L2, not DRAM
#pragma unroll
        for (int s = 0; s < 6; s++)
            asm volatile("prefetch.global.L2 [%0];"
                         :: "l"(bptr + (size_t)s*SST + 256));
        mma_step6(acc, A0h, A0l, B0);
        ap4 += 128; bptr += 64;
        A0h = __ldcg(ap4); A0l = __ldcg(ap4+1);
#pragma unroll
        for (int s = 0; s < 6; s++) B0[s] = __ldg(bptr + (size_t)s*SST);
        mma_step6(acc, A1h, A1l, B1);
        A1h = __ldcg(ap4+64); A1l = __ldcg(ap4+65);
#pragma unroll
        for (int s = 0; s < 6; s++) B1[s] = __ldg(bptr + (size_t)s*SST + 32);
    }
    mma_step6(acc, A0h, A0l, B0);
    mma_step6(acc, A1h, A1l, B1);

    if (kh){
#pragma unroll
        for (int n = 0; n < 2; n++)
#pragma unroll
            for (int g = 0; g < 3; g++)
#pragma unroll
                for (int i = 0; i < 4; i++)
                    sred[(((kh-1)*4 + mt)*32 + l)*24 + (n*3+g)*4 + i] = acc[n][g][i];
    }
    __syncthreads();
    if (!kh){
#pragma unroll
        for (int s = 0; s < 3; s++)
#pragma unroll
            for (int n = 0; n < 2; n++)
#pragma unroll
                for (int g = 0; g < 3; g++)
#pragma unroll
                    for (int i = 0; i < 4; i++)
                        acc[n][g][i] += sred[((s*4 + mt)*32 + l)*24 + (n*3+g)*4 + i];
    }
}

// ---------------- epilogues (R13 verbatim) ----------------------------------------
__device__ __forceinline__ void epiA(const float acc[2][3][4],
    const float* __restrict__ bias, const float* __restrict__ gi,
    const float* __restrict__ Woh, int ldw, const int* __restrict__ idx,
    const float* __restrict__ Hfp, float* __restrict__ outH,
    uint32_t* __restrict__ Frag)
{
    int tid = threadIdx.x, jt = blockIdx.x;
    int mt = tid >> 5, l = tid & 31;
    int q = l >> 2, tp = l & 3;
    int m0 = mt*16 + q, m1 = m0 + 8;
    int ix0 = __ldcg(idx + m0), ix1 = __ldcg(idx + m1);
    int lp = q*4 + tp;
    uint32_t* fb = Frag + (((size_t)mt*K16N + jt)*32 + lp)*8;
#pragma unroll
    for (int nh = 0; nh < 2; nh++){
        int c0 = jt*16 + nh*8 + 2*tp, c1 = c0 + 1;
        float br = __ldg(bias+c0), brX = __ldg(bias+c1);
        float bz = __ldg(bias+Hd+c0), bzX = __ldg(bias+Hd+c1);
        float bn = __ldg(bias+2*Hd+c0), bnX = __ldg(bias+2*Hd+c1);
        float hout[4];
#pragma unroll
        for (int v = 0; v < 4; v++){
            int b = (v & 2) ? m1 : m0;
            int c = (v & 1) ? c1 : c0;
            int ix = (v & 2) ? ix1 : ix0;
            float gir = __ldcg(gi + (size_t)b*G3 + c) + __ldg(Woh + (size_t)c*ldw + ix);
            float giz = __ldcg(gi + (size_t)b*G3 + Hd + c) + __ldg(Woh + (size_t)(Hd+c)*ldw + ix);
            float gin = __ldcg(gi + (size_t)b*G3 + 2*Hd + c) + __ldg(Woh + (size_t)(2*Hd+c)*ldw + ix);
            float ghr = acc[nh][0][v] + ((v & 1) ? brX : br);
            float ghz = acc[nh][1][v] + ((v & 1) ? bzX : bz);
            float ghn = acc[nh][2][v] + ((v & 1) ? bnX : bn);
            float r = sigm_f(gir + ghr);
            float u = sigm_f(giz + ghz);
            float n = tanh_f(gin + r*ghn);
            float hp = __ldcg(Hfp + (size_t)b*Hd + c);
            hout[v] = (1.f - u)*n + u*hp;
            outH[(size_t)b*Hd + c] = hout[v];
        }
        uint32_t hi0, lo0, hi1, lo1;
        split2(hout[0], hout[1], hi0, lo0);
        split2(hout[2], hout[3], hi1, lo1);
        fb[nh*2 + 0] = hi0; fb[nh*2 + 1] = hi1;
        fb[4 + nh*2 + 0] = lo0; fb[4 + nh*2 + 1] = lo1;
    }
}

__device__ __forceinline__ void epi2(const float acc[2][3][4], const float gh2[2][3][4],
    const float* __restrict__ bi, const float* __restrict__ bh,
    const float* __restrict__ Hfp, float* __restrict__ outH,
    uint32_t* __restrict__ Frag)
{
    int tid = threadIdx.x, jt = blockIdx.x;
    int mt = tid >> 5, l = tid & 31;
    int q = l >> 2, tp = l & 3;
    int m0 = mt*16 + q, m1 = m0 + 8;
    int lp = q*4 + tp;
    uint32_t* fb = Frag + (((size_t)mt*K16N + jt)*32 + lp)*8;
#pragma unroll
    for (int nh = 0; nh < 2; nh++){
        int c0 = jt*16 + nh*8 + 2*tp, c1 = c0 + 1;
        float hout[4];
#pragma unroll
        for (int v = 0; v < 4; v++){
            int b = (v & 2) ? m1 : m0;
            int c = (v & 1) ? c1 : c0;
            float gir = acc[nh][0][v] + __ldg(bi + c);
            float giz = acc[nh][1][v] + __ldg(bi + Hd + c);
            float gin = acc[nh][2][v] + __ldg(bi + 2*Hd + c);
            float ghr = gh2[nh][0][v] + __ldg(bh + c);
            float ghz = gh2[nh][1][v] + __ldg(bh + Hd + c);
            float ghn = gh2[nh][2][v] + __ldg(bh + 2*Hd + c);
            float r = sigm_f(gir + ghr);
            float u = sigm_f(giz + ghz);
            float n = tanh_f(gin + r*ghn);
            float hp = __ldcg(Hfp + (size_t)b*Hd + c);
            hout[v] = (1.f - u)*n + u*hp;
            outH[(size_t)b*Hd + c] = hout[v];
        }
        uint32_t hi0, lo0, hi1, lo1;
        split2(hout[0], hout[1], hi0, lo0);
        split2(hout[2], hout[3], hi1, lo1);
        fb[nh*2 + 0] = hi0; fb[nh*2 + 1] = hi1;
        fb[4 + nh*2 + 0] = lo0; fb[4 + nh*2 + 1] = lo1;
    }
}

// ---------------- logits bodies (flag-producing) ----------------------------------
__device__ __forceinline__ void rhy_body(const float* __restrict__ Hn,
    const float* __restrict__ wo0, const float* __restrict__ bo0,
    float* __restrict__ rlo, int* __restrict__ ridx, float* sm)
{
    int b = blockIdx.x, tid = threadIdx.x;
    if (tid < 384){
        int g = tid >> 7, s = tid & 127;
        float p = 0.f;
        for (int k = s; k < Hd; k += 128)
            p += __ldcg(Hn + (size_t)b*Hd + k) * __ldg(wo0 + (size_t)g*Hd + k);
        sm[tid] = p;
    }
    __syncthreads();
    for (int off = 64; off > 0; off >>= 1){
        if (tid < 384 && (tid & 127) < off) sm[tid] += sm[tid + off];
        __syncthreads();
    }
    if (tid == 0){
        float l0 = sm[0] + __ldg(bo0+0), l1 = sm[128] + __ldg(bo0+1), l2 = sm[256] + __ldg(bo0+2);
        float m = fmaxf(l0, fmaxf(l1, l2));
        float z = m + logf(expf(l0-m) + expf(l1-m) + expf(l2-m));
        rlo[b*3+0] = l0 - z; rlo[b*3+1] = l1 - z; rlo[b*3+2] = l2 - z;
        int ix = 0; float bv = l0;
        if (l1 > bv){ bv = l1; ix = 1; }
        if (l2 > bv){ bv = l2; ix = 2; }
        ridx[b] = ix;
        __threadfence();
        atomicAdd(&g_rfl, 1);
    }
    __syncthreads();
}

__device__ __forceinline__ void mel_body(const float* __restrict__ Hn,
    const float* __restrict__ wo1, const float* __restrict__ bo1,
    float* __restrict__ outmel, int t, int* __restrict__ midx, float* sm)
{
    float* hs = sm;
    float* ls = sm + 2048;
    float* red = sm + 2208;
    int b = blockIdx.x, tid = threadIdx.x;
    for (int k = tid; k < Hd; k += 512) hs[k] = __ldcg(Hn + (size_t)b*Hd + k);
    __syncthreads();
    int w = tid >> 5, l = tid & 31;
    const float4* h4 = (const float4*)hs;
    for (int r = w; r < MELN; r += 16){
        const float4* w4 = (const float4*)(wo1 + (size_t)r*Hd);
        float s = 0.f;
        for (int c = l; c < Hd/4; c += 32){
            float4 a = h4[c], q = __ldg(w4 + c);
            s += a.x*q.x + a.y*q.y + a.z*q.z + a.w*q.w;
        }
#pragma unroll
        for (int off = 16; off > 0; off >>= 1) s += __shfl_xor_sync(0xffffffffu, s, off);
        if (l == 0) ls[r] = s + __ldg(bo1 + r);
    }
    __syncthreads();
    red[tid] = (tid < MELN) ? ls[tid] : -3.4e38f;
    __syncthreads();
    for (int off = 256; off > 0; off >>= 1){
        if (tid < off) red[tid] = fmaxf(red[tid], red[tid + off]);
        __syncthreads();
    }
    float m = red[0];
    __syncthreads();
    red[tid] = (tid < MELN) ? expf(ls[tid] - m) : 0.f;
    __syncthreads();
    for (int off = 256; off > 0; off >>= 1){
        if (tid < off) red[tid] += red[tid + off];
        __syncthreads();
    }
    float z = m + logf(red[0]);
    if (tid < MELN)
        outmel[((size_t)b*TT + t)*MELN + tid] = ls[tid] - z;
    if (tid == 0){
        int ix = 0; float bv = ls[0];
        for (int c = 1; c < MELN; c++) if (ls[c] > bv){ bv = ls[c]; ix = c; }
        midx[b] = ix;
        __threadfence();
        atomicAdd(&g_mfl, 1);
    }
    __syncthreads();
}

__device__ __forceinline__ void gi1t_body(const float* __restrict__ cond,
                                          const float* __restrict__ w_ih1)
{
    int id = blockIdx.x*512 + threadIdx.x;
#pragma unroll 1
    for (int r = 0; r < 3; r++){
        int id2 = id + r*65536;
        int t = id2 / G3;
        int n = id2 - t*G3;
        float wr[RHYN], wc[CHN];
#pragma unroll
        for (int j = 0; j < RHYN; j++) wr[j] = __ldg(w_ih1 + (size_t)n*273 + MELN + j);
#pragma unroll
        for (int j = 0; j < CHN; j++)
            wc[j] = __ldg(w_ih1 + (size_t)n*273 + MELN + RHYN + 128 + j);
#pragma unroll 1
        for (int b = 0; b < NB; b++){
            float s = g_gi1z[(size_t)b*G3 + n];
            const float* rl = g_rlo + (t*NB + b)*RHYN;
            s += __ldcg(rl)*wr[0] + __ldcg(rl+1)*wr[1] + __ldcg(rl+2)*wr[2];
            const float* c = cond + ((size_t)b*TT + t)*CHN;
#pragma unroll
            for (int j = 0; j < CHN; j++) s += __ldg(c + j)*wc[j];
            g_gi1t[((size_t)t*NB + b)*G3 + n] = s;
        }
    }
}

// ---------------- persistent main kernel ------------------------------------------
__global__ __launch_bounds__(512, 1) void k_main(
    const float* __restrict__ w_ih0, const float* __restrict__ b_hh0,
    const float* __restrict__ w_ih1, const float* __restrict__ b_hh1,
    const float* __restrict__ b_ih2, const float* __restrict__ b_hh2,
    const float* __restrict__ wo0, const float* __restrict__ bo0,
    const float* __restrict__ wo1, const float* __restrict__ bo1,
    const float* __restrict__ cond, float* __restrict__ out,
    const float* __restrict__ z1, const float* __restrict__ z2,
    const float* __restrict__ wi0, const float* __restrict__ bi0,
    const float* __restrict__ wi1, const float* __restrict__ bi1,
    const float* __restrict__ b_ih0, const float* __restrict__ b_ih1,
    const float* __restrict__ w_hh0, const float* __restrict__ w_hh1,
    const float* __restrict__ w_ih2, const float* __restrict__ w_hh2)
{
    __shared__ float pool[9216];
    int tgt = 0;
    int tid = threadIdx.x, bid = blockIdx.x;
    float acc[2][3][4];

    // ================= phase 0: precompute (mv jobs + weight pack) =================
    {
        const float *zsrc, *W, *bias;
        int ldw, off, isH, nbase;
        float* dsth = 0; uint32_t* dstf = 0; float* dstg = 0;
        if (bid < 16){ zsrc=z2; W=wi0; bias=bi0; ldw=128; off=0; isH=1;
                       dsth=g_h; dstf=g_hfrag[0]; nbase=bid*128; }
        else if (bid < 32){ zsrc=z1; W=wi1; bias=bi1; ldw=128; off=0; isH=1;
                       dsth=g_ha; dstf=g_hafrag[0]; nbase=(bid-16)*128; }
        else if (bid < 80){ zsrc=z2; W=w_ih0; bias=b_ih0; ldw=131; off=RHYN; isH=0;
                       dstg=g_gic0; nbase=(bid-32)*128; }
        else { zsrc=z1; W=w_ih1; bias=b_ih1; ldw=273; off=MELN+RHYN; isH=0;
                       dstg=g_gi1z; nbase=(bid-80)*128; }
        for (int i = tid; i < 8192; i += 512)
            pool[(i & 127)*64 + (i >> 7)] = __ldg(zsrc + (i >> 7)*128 + (i & 127));
        __syncthreads();
        int np = tid >> 3, bg = tid & 7;
        int n0 = nbase + np*2;
        const float* w0 = W + (size_t)n0*ldw + off;
        const float* w1 = w0 + ldw;
        float a0[8], a1[8];
#pragma unroll
        for (int j = 0; j < 8; j++){ a0[j] = 0.f; a1[j] = 0.f; }
        for (int k = 0; k < 128; k++){
            float u = __ldg(w0 + k), v = __ldg(w1 + k);
            const float* zp = pool + k*64 + bg*8;
#pragma unroll
            for (int j = 0; j < 8; j++){
                float xv = zp[j];
                a0[j] += xv*u; a1[j] += xv*v;
            }
        }
        float b0v = __ldg(bias + n0), b1v = __ldg(bias + n0 + 1);
#pragma unroll
        for (int j = 0; j < 8; j++){
            int b = bg*8 + j;
            float v0 = a0[j] + b0v, v1 = a1[j] + b1v;
            if (isH){
                v0 = tanh_f(v0); v1 = tanh_f(v1);
                *(float2*)&dsth[(size_t)b*Hd + n0] = make_float2(v0, v1);
                frag_write(dstf, b, n0, v0, v1);
            } else {
                *(float2*)&dstg[(size_t)b*G3 + n0] = make_float2(v0, v1);
            }
        }
        __syncthreads();
        const float* Ws[4] = { w_hh0, w_hh1, w_ih2, w_hh2 };
        uint4* Os[4] = { g_Bp0, g_Bp1, g_Bp2i, g_Bp2h };
#pragma unroll 1
        for (int mat = 0; mat < 4; mat++){
            const float* W4 = Ws[mat];
            uint4* o4 = Os[mat];
#pragma unroll 1
            for (int it = 0; it < 48; it++){
                int id = (bid*512 + tid) + it*65536;
                int l = id & 31, nt = id >> 12;
                int P = nt*8 + (l >> 2);
                int jt = P/48, rem = P%48, g = rem >> 4, c = rem & 15;
                int k16 = (id >> 5) & 127;
                const float* wr = W4 + (size_t)(g*Hd + jt*16 + c)*Hd + k16*16 + 2*(l&3);
                uint4 vv;
                split2(__ldg(wr), __ldg(wr+1), vv.x, vv.z);
                split2(__ldg(wr+8), __ldg(wr+9), vv.y, vv.w);
                o4[id] = vv;
            }
        }
        gbar(tgt);
    }

    // ================= rhythm phase (1 barrier/step) ===============================
#pragma unroll 1
    for (int t = 0; t < TT; t++){
        int cu = t & 1, nx = cu ^ 1;
        if (bid < NB && t > 0)
            rhy_body(g_h + (size_t)cu*NBHd, wo0, bo0,
                     g_rlo + (t-1)*NB*RHYN, g_ridx + t*NB, pool);
        gemm_acc(g_Bp0, g_hfrag[cu], acc, pool);
        if (tid == 0) spinflag(&g_rfl, 64*t);
        __syncthreads();
        if (tid < 128)
            epiA(acc, b_hh0, g_gic0, w_ih0, 131, g_ridx + t*NB,
                 g_h + (size_t)cu*NBHd, g_h + (size_t)nx*NBHd, g_hfrag[nx]);
        gbar(tgt);
    }
    if (bid < NB)
        rhy_body(g_h + (size_t)0*NBHd, wo0, bo0,
                 g_rlo + 31*NB*RHYN, g_ridx + 32*NB, pool);
    gbar(tgt);
    gi1t_body(cond, w_ih1);
    gbar(tgt);

    // ================= melody phase (2 barriers/step) ==============================
#pragma unroll 1
    for (int t = 0; t < TT; t++){
        int cu = t & 1, nx = cu ^ 1;
        if (bid < NB && t > 0)
            mel_body(g_hb + (size_t)cu*NBHd, wo1, bo1, out, t-1,
                     g_midx + t*NB, pool);
        gemm_acc(g_Bp1, g_hafrag[cu], acc, pool);
        if (tid == 0) spinflag(&g_mfl, 64*t);
        __syncthreads();
        if (tid < 128)
            epiA(acc, b_hh1, g_gi1t + (size_t)t*NB*G3, w_ih1, 273, g_midx + t*NB,
                 g_ha + (size_t)cu*NBHd, g_ha + (size_t)nx*NBHd, g_hafrag[nx]);
        gbar(tgt);
        const uint32_t* fbin = (t == 0) ? g_hafrag[1] : g_hbfrag[cu];
        const float* hbprev = (t == 0) ? (g_ha + (size_t)NBHd) : (g_hb + (size_t)cu*NBHd);
        gemm_acc(g_Bp2h, fbin, acc, pool);
        float gh2[2][3][4];
        if (tid < 128){
#pragma unroll
            for (int n = 0; n < 2; n++)
#pragma unroll
                for (int g = 0; g < 3; g++)
#pragma unroll
                    for (int i = 0; i < 4; i++) gh2[n][g][i] = acc[n][g][i];
        }
        gemm_acc(g_Bp2i, g_hafrag[nx], acc, pool);
        if (tid < 128)
            epi2(acc, gh2, b_ih2, b_hh2, hbprev,
                 g_hb + (size_t)nx*NBHd, g_hbfrag[nx]);
        gbar(tgt);
    }
    if (bid < NB)
        mel_body(g_hb + (size_t)0*NBHd, wo1, bo1, out, 31, g_midx + 32*NB, pool);
}

// ---------------- host driver ------------------------------------------------------
extern "C" void kernel_launch(void* const* d_in, const int* in_sizes, int n_in,
                              void* d_out, int out_size)
{
    const float* z1    = (const float*)d_in[0];
    const float* z2    = (const float*)d_in[1];
    const float* cond  = (const float*)d_in[2];
    const float* w_ih0 = (const float*)d_in[3];
    const float* w_hh0 = (const float*)d_in[4];
    const float* b_ih0 = (const float*)d_in[5];
    const float* b_hh0 = (const float*)d_in[6];
    const float* w_ih1 = (const float*)d_in[7];
    const float* w_hh1 = (const float*)d_in[8];
    const float* b_ih1 = (const float*)d_in[9];
    const float* b_hh1 = (const float*)d_in[10];
    const float* w_ih2 = (const float*)d_in[11];
    const float* w_hh2 = (const float*)d_in[12];
    const float* b_ih2 = (const float*)d_in[13];
    const float* b_hh2 = (const float*)d_in[14];
    const float* wi0   = (const float*)d_in[15];
    const float* bi0   = (const float*)d_in[16];
    const float* wo0   = (const float*)d_in[17];
    const float* bo0   = (const float*)d_in[18];
    const float* wi1   = (const float*)d_in[19];
    const float* bi1   = (const float*)d_in[20];
    const float* wo1   = (const float*)d_in[21];
    const float* bo1   = (const float*)d_in[22];
    float* out = (float*)d_out;

    k_init<<<1, 64>>>();
    k_main<<<128, 512>>>(w_ih0, b_hh0, w_ih1, b_hh1, b_ih2, b_hh2,
                         wo0, bo0, wo1, bo1, cond, out,
                         z1, z2, wi0, bi0, wi1, bi1, b_ih0, b_ih1,
                         w_hh0, w_hh1, w_ih2, w_hh2);
}

// round 16
// speedup vs baseline: 1.2849x; 1.0413x over previous
#include <cuda_runtime.h>
#include <cuda_bf16.h>
#include <math.h>
#include <stdint.h>
#include <stddef.h>

#define NB 64
#define Hd 2048
#define G3 6144
#define TT 32
#define MELN 130
#define CHN 12
#define RHYN 3
#define NBHd (NB*Hd)
#define K16N 128
#define FRAGU32 (4*128*32*8)
#define BPKSZ 3145728
#define SST (128*32)

// ---------------- device globals -------------------------------------------------
__device__ float g_h[2*NBHd], g_ha[2*NBHd], g_hb[2*NBHd];
__device__ float g_gic0[NB*G3], g_gi1z[NB*G3];
__device__ float g_gi1t[(size_t)TT*NB*G3];
__device__ float g_rlo[TT*NB*RHYN];
__device__ float g_rpart[NB*3];
__device__ float g_mls[NB*132];
__device__ int g_ridx[(TT+1)*NB], g_midx[(TT+1)*NB];
__device__ int g_bar, g_rfl, g_mfl;
__device__ int g_rpf[NB], g_mpf[NB];
__device__ uint4 g_Bp0[BPKSZ], g_Bp1[BPKSZ], g_Bp2i[BPKSZ], g_Bp2h[BPKSZ];
__device__ uint32_t g_hfrag[2][FRAGU32], g_hafrag[2][FRAGU32], g_hbfrag[2][FRAGU32];

// ---------------- helpers ---------------------------------------------------------
__device__ __forceinline__ float sigm_f(float x){ return 1.0f/(1.0f+expf(-x)); }
__device__ __forceinline__ float tanh_f(float x){ return 1.0f-2.0f/(expf(2.0f*x)+1.0f); }

__device__ __forceinline__ uint32_t packbf2(float x, float y){
    __nv_bfloat162 v = __floats2bfloat162_rn(x, y);
    return *reinterpret_cast<uint32_t*>(&v);
}
__device__ __forceinline__ void split2(float x, float y, uint32_t& hi, uint32_t& lo){
    __nv_bfloat16 hx = __float2bfloat16(x), hy = __float2bfloat16(y);
    float rx = x - __bfloat162float(hx);
    float ry = y - __bfloat162float(hy);
    __nv_bfloat162 H; H.x = hx; H.y = hy;
    hi = *reinterpret_cast<uint32_t*>(&H);
    lo = packbf2(rx, ry);
}
__device__ __forceinline__ void mma16816(float* d, uint32_t a0, uint32_t a1,
                                         uint32_t a2, uint32_t a3,
                                         uint32_t b0, uint32_t b1){
    asm volatile(
        "mma.sync.aligned.m16n8k16.row.col.f32.bf16.bf16.f32 "
        "{%0,%1,%2,%3}, {%4,%5,%6,%7}, {%8,%9}, {%0,%1,%2,%3};"
        : "+f"(d[0]), "+f"(d[1]), "+f"(d[2]), "+f"(d[3])
        : "r"(a0), "r"(a1), "r"(a2), "r"(a3), "r"(b0), "r"(b1));
}
__device__ __forceinline__ void mma_step6(float acc[2][3][4], const uint4& ah,
                                          const uint4& al, const uint4 b[6]){
    mma16816(acc[0][0], ah.x,ah.y,ah.z,ah.w, b[0].x,b[0].y);
    mma16816(acc[0][1], ah.x,ah.y,ah.z,ah.w, b[2].x,b[2].y);
    mma16816(acc[0][2], ah.x,ah.y,ah.z,ah.w, b[4].x,b[4].y);
    mma16816(acc[1][0], ah.x,ah.y,ah.z,ah.w, b[1].x,b[1].y);
    mma16816(acc[1][1], ah.x,ah.y,ah.z,ah.w, b[3].x,b[3].y);
    mma16816(acc[1][2], ah.x,ah.y,ah.z,ah.w, b[5].x,b[5].y);
    mma16816(acc[0][0], ah.x,ah.y,ah.z,ah.w, b[0].z,b[0].w);
    mma16816(acc[0][1], ah.x,ah.y,ah.z,ah.w, b[2].z,b[2].w);
    mma16816(acc[0][2], ah.x,ah.y,ah.z,ah.w, b[4].z,b[4].w);
    mma16816(acc[1][0], ah.x,ah.y,ah.z,ah.w, b[1].z,b[1].w);
    mma16816(acc[1][1], ah.x,ah.y,ah.z,ah.w, b[3].z,b[3].w);
    mma16816(acc[1][2], ah.x,ah.y,ah.z,ah.w, b[5].z,b[5].w);
    mma16816(acc[0][0], al.x,al.y,al.z,al.w, b[0].x,b[0].y);
    mma16816(acc[0][1], al.x,al.y,al.z,al.w, b[2].x,b[2].y);
    mma16816(acc[0][2], al.x,al.y,al.z,al.w, b[4].x,b[4].y);
    mma16816(acc[1][0], al.x,al.y,al.z,al.w, b[1].x,b[1].y);
    mma16816(acc[1][1], al.x,al.y,al.z,al.w, b[3].x,b[3].y);
    mma16816(acc[1][2], al.x,al.y,al.z,al.w, b[5].x,b[5].y);
}

__device__ __forceinline__ void gbar(int& tgt){
    __threadfence();
    __syncthreads();
    if (threadIdx.x == 0){
        tgt += 128;
        atomicAdd(&g_bar, 1);
        int v;
        do {
            asm volatile("ld.acquire.gpu.global.b32 %0, [%1];" : "=r"(v) : "l"(&g_bar));
        } while (v < tgt);
    }
    __syncthreads();
}
__device__ __forceinline__ void spinflag(int* f, int target){
    int v;
    do {
        asm volatile("ld.acquire.gpu.global.b32 %0, [%1];" : "=r"(v) : "l"(f));
    } while (v < target);
}

// ---------------- init kernel -----------------------------------------------------
__global__ void k_init(){
    int i = threadIdx.x;
    if (i == 0){ g_bar = 0; g_rfl = 0; g_mfl = 0; }
    if (i < NB){
        g_ridx[i] = RHYN-1; g_midx[i] = MELN-1;
        g_rpf[i] = 0; g_mpf[i] = 0;
    }
}

// ---------------- frag mapping (b, u0-even) ---------------------------------------
__device__ __forceinline__ void frag_write(uint32_t* __restrict__ Frag,
                                           int b, int u0, float h0, float h1)
{
    uint32_t hi, lo; split2(h0, h1, hi, lo);
    int mt = b >> 4, rw = b & 15, q = rw & 7, rs = rw >> 3;
    int k16 = u0 >> 4, kk = u0 & 15, tp = (kk & 7) >> 1;
    int r = ((kk >= 8) ? 2 : 0) + rs;
    uint32_t* fb = Frag + (((size_t)mt*128 + k16)*32 + q*4 + tp)*8;
    fb[r] = hi; fb[r + 4] = lo;
}

// ---------------- GEMM tile (R13 verbatim) ----------------------------------------
__device__ __forceinline__ void gemm_acc(const uint4* __restrict__ Bpk,
                                         const uint32_t* __restrict__ Af,
                                         float acc[2][3][4], float* sred)
{
    __syncthreads();
    int tid = threadIdx.x, jt = blockIdx.x;
    int w = tid >> 5, l = tid & 31;
    int mt = w & 3, kh = w >> 2;
#pragma unroll
    for (int n = 0; n < 2; n++)
#pragma unroll
        for (int g = 0; g < 3; g++)
#pragma unroll
            for (int i = 0; i < 4; i++) acc[n][g][i] = 0.f;

    const uint4* bptr = Bpk + ((size_t)(jt*6)*K16N + kh*32)*32 + l;
    const uint4* ap4 = (const uint4*)(Af + (((size_t)mt*K16N + kh*32)*32 + l)*8);

    uint4 A0h = __ldcg(ap4), A0l = __ldcg(ap4+1);
    uint4 A1h = __ldcg(ap4+64), A1l = __ldcg(ap4+65);
    uint4 B0[6], B1[6];
#pragma unroll
    for (int s = 0; s < 6; s++){
        B0[s] = __ldg(bptr + (size_t)s*SST);
        B1[s] = __ldg(bptr + (size_t)s*SST + 32);
    }
#pragma unroll 1
    for (int k16 = 0; k16 < 30; k16 += 2){
        mma_step6(acc, A0h, A0l, B0);
        ap4 += 128; bptr += 64;
        A0h = __ldcg(ap4); A0l = __ldcg(ap4+1);
#pragma unroll
        for (int s = 0; s < 6; s++) B0[s] = __ldg(bptr + (size_t)s*SST);
        mma_step6(acc, A1h, A1l, B1);
        A1h = __ldcg(ap4+64); A1l = __ldcg(ap4+65);
#pragma unroll
        for (int s = 0; s < 6; s++) B1[s] = __ldg(bptr + (size_t)s*SST + 32);
    }
    mma_step6(acc, A0h, A0l, B0);
    mma_step6(acc, A1h, A1l, B1);

    if (kh){
#pragma unroll
        for (int n = 0; n < 2; n++)
#pragma unroll
            for (int g = 0; g < 3; g++)
#pragma unroll
                for (int i = 0; i < 4; i++)
                    sred[(((kh-1)*4 + mt)*32 + l)*24 + (n*3+g)*4 + i] = acc[n][g][i];
    }
    __syncthreads();
    if (!kh){
#pragma unroll
        for (int s = 0; s < 3; s++)
#pragma unroll
            for (int n = 0; n < 2; n++)
#pragma unroll
                for (int g = 0; g < 3; g++)
#pragma unroll
                    for (int i = 0; i < 4; i++)
                        acc[n][g][i] += sred[((s*4 + mt)*32 + l)*24 + (n*3+g)*4 + i];
    }
}

// ---------------- epilogues (R13 verbatim) ----------------------------------------
__device__ __forceinline__ void epiA(const float acc[2][3][4],
    const float* __restrict__ bias, const float* __restrict__ gi,
    const float* __restrict__ Woh, int ldw, const int* __restrict__ idx,
    const float* __restrict__ Hfp, float* __restrict__ outH,
    uint32_t* __restrict__ Frag)
{
    int tid = threadIdx.x, jt = blockIdx.x;
    int mt = tid >> 5, l = tid & 31;
    int q = l >> 2, tp = l & 3;
    int m0 = mt*16 + q, m1 = m0 + 8;
    int ix0 = __ldcg(idx + m0), ix1 = __ldcg(idx + m1);
    int lp = q*4 + tp;
    uint32_t* fb = Frag + (((size_t)mt*K16N + jt)*32 + lp)*8;
#pragma unroll
    for (int nh = 0; nh < 2; nh++){
        int c0 = jt*16 + nh*8 + 2*tp, c1 = c0 + 1;
        float br = __ldg(bias+c0), brX = __ldg(bias+c1);
        float bz = __ldg(bias+Hd+c0), bzX = __ldg(bias+Hd+c1);
        float bn = __ldg(bias+2*Hd+c0), bnX = __ldg(bias+2*Hd+c1);
        float hout[4];
#pragma unroll
        for (int v = 0; v < 4; v++){
            int b = (v & 2) ? m1 : m0;
            int c = (v & 1) ? c1 : c0;
            int ix = (v & 2) ? ix1 : ix0;
            float gir = __ldcg(gi + (size_t)b*G3 + c) + __ldg(Woh + (size_t)c*ldw + ix);
            float giz = __ldcg(gi + (size_t)b*G3 + Hd + c) + __ldg(Woh + (size_t)(Hd+c)*ldw + ix);
            float gin = __ldcg(gi + (size_t)b*G3 + 2*Hd + c) + __ldg(Woh + (size_t)(2*Hd+c)*ldw + ix);
            float ghr = acc[nh][0][v] + ((v & 1) ? brX : br);
            float ghz = acc[nh][1][v] + ((v & 1) ? bzX : bz);
            float ghn = acc[nh][2][v] + ((v & 1) ? bnX : bn);
            float r = sigm_f(gir + ghr);
            float u = sigm_f(giz + ghz);
            float n = tanh_f(gin + r*ghn);
            float hp = __ldcg(Hfp + (size_t)b*Hd + c);
            hout[v] = (1.f - u)*n + u*hp;
            outH[(size_t)b*Hd + c] = hout[v];
        }
        uint32_t hi0, lo0, hi1, lo1;
        split2(hout[0], hout[1], hi0, lo0);
        split2(hout[2], hout[3], hi1, lo1);
        fb[nh*2 + 0] = hi0; fb[nh*2 + 1] = hi1;
        fb[4 + nh*2 + 0] = lo0; fb[4 + nh*2 + 1] = lo1;
    }
}

__device__ __forceinline__ void epi2(const float acc[2][3][4], const float gh2[2][3][4],
    const float* __restrict__ bi, const float* __restrict__ bh,
    const float* __restrict__ Hfp, float* __restrict__ outH,
    uint32_t* __restrict__ Frag)
{
    int tid = threadIdx.x, jt = blockIdx.x;
    int mt = tid >> 5, l = tid & 31;
    int q = l >> 2, tp = l & 3;
    int m0 = mt*16 + q, m1 = m0 + 8;
    int lp = q*4 + tp;
    uint32_t* fb = Frag + (((size_t)mt*K16N + jt)*32 + lp)*8;
#pragma unroll
    for (int nh = 0; nh < 2; nh++){
        int c0 = jt*16 + nh*8 + 2*tp, c1 = c0 + 1;
        float hout[4];
#pragma unroll
        for (int v = 0; v < 4; v++){
            int b = (v & 2) ? m1 : m0;
            int c = (v & 1) ? c1 : c0;
            float gir = acc[nh][0][v] + __ldg(bi + c);
            float giz = acc[nh][1][v] + __ldg(bi + Hd + c);
            float gin = acc[nh][2][v] + __ldg(bi + 2*Hd + c);
            float ghr = gh2[nh][0][v] + __ldg(bh + c);
            float ghz = gh2[nh][1][v] + __ldg(bh + Hd + c);
            float ghn = gh2[nh][2][v] + __ldg(bh + 2*Hd + c);
            float r = sigm_f(gir + ghr);
            float u = sigm_f(giz + ghz);
            float n = tanh_f(gin + r*ghn);
            float hp = __ldcg(Hfp + (size_t)b*Hd + c);
            hout[v] = (1.f - u)*n + u*hp;
            outH[(size_t)b*Hd + c] = hout[v];
        }
        uint32_t hi0, lo0, hi1, lo1;
        split2(hout[0], hout[1], hi0, lo0);
        split2(hout[2], hout[3], hi1, lo1);
        fb[nh*2 + 0] = hi0; fb[nh*2 + 1] = hi1;
        fb[4 + nh*2 + 0] = lo0; fb[4 + nh*2 + 1] = lo1;
    }
}

// ---------------- logits bodies: pair-split across all 128 blocks ------------------
// rhythm: block pair (b, b+64) each does half the K range; bid<64 finalizes.
__device__ __forceinline__ void rhy_body(const float* __restrict__ Hn,
    const float* __restrict__ wo0, const float* __restrict__ bo0,
    float* __restrict__ rlo, int* __restrict__ ridx, float* sm, int c)
{
    int bid = blockIdx.x, tid = threadIdx.x;
    int half = (bid >= NB);
    int b = half ? bid - NB : bid;
    int kbase = half*1024;
    if (tid < 384){
        int g = tid >> 7, s = tid & 127;
        float p = 0.f;
        for (int k = kbase + s; k < kbase + 1024; k += 128)
            p += __ldcg(Hn + (size_t)b*Hd + k) * __ldg(wo0 + (size_t)g*Hd + k);
        sm[tid] = p;
    }
    __syncthreads();
    for (int off = 64; off > 0; off >>= 1){
        if (tid < 384 && (tid & 127) < off) sm[tid] += sm[tid + off];
        __syncthreads();
    }
    if (half){
        if (tid == 0){
            g_rpart[b*3 + 0] = sm[0];
            g_rpart[b*3 + 1] = sm[128];
            g_rpart[b*3 + 2] = sm[256];
            __threadfence();
            atomicAdd(&g_rpf[b], 1);
        }
        __syncthreads();
        return;
    }
    if (tid == 0){
        spinflag(&g_rpf[b], c);
        float l0 = sm[0]   + __ldcg(&g_rpart[b*3+0]) + __ldg(bo0+0);
        float l1 = sm[128] + __ldcg(&g_rpart[b*3+1]) + __ldg(bo0+1);
        float l2 = sm[256] + __ldcg(&g_rpart[b*3+2]) + __ldg(bo0+2);
        float m = fmaxf(l0, fmaxf(l1, l2));
        float z = m + logf(expf(l0-m) + expf(l1-m) + expf(l2-m));
        rlo[b*3+0] = l0 - z; rlo[b*3+1] = l1 - z; rlo[b*3+2] = l2 - z;
        int ix = 0; float bv = l0;
        if (l1 > bv){ bv = l1; ix = 1; }
        if (l2 > bv){ bv = l2; ix = 2; }
        ridx[b] = ix;
        __threadfence();
        atomicAdd(&g_rfl, 1);
    }
    __syncthreads();
}

// melody: pair splits 130 rows by parity; bid<64 finalizes softmax/argmax/output.
__device__ __forceinline__ void mel_body(const float* __restrict__ Hn,
    const float* __restrict__ wo1, const float* __restrict__ bo1,
    float* __restrict__ outmel, int t, int* __restrict__ midx, float* sm, int c)
{
    float* hs = sm;
    float* ls = sm + 2048;
    float* red = sm + 2208;
    int bid = blockIdx.x, tid = threadIdx.x;
    int half = (bid >= NB);
    int b = half ? bid - NB : bid;
    for (int k = tid; k < Hd; k += 512) hs[k] = __ldcg(Hn + (size_t)b*Hd + k);
    __syncthreads();
    int w = tid >> 5, l = tid & 31;
    const float4* h4 = (const float4*)hs;
    for (int j = w; 2*j + half < MELN; j += 16){
        int r = 2*j + half;
        const float4* w4 = (const float4*)(wo1 + (size_t)r*Hd);
        float s = 0.f;
        for (int cc = l; cc < Hd/4; cc += 32){
            float4 a = h4[cc], q = __ldg(w4 + cc);
            s += a.x*q.x + a.y*q.y + a.z*q.z + a.w*q.w;
        }
#pragma unroll
        for (int off = 16; off > 0; off >>= 1) s += __shfl_xor_sync(0xffffffffu, s, off);
        if (l == 0) g_mls[b*132 + r] = s + __ldg(bo1 + r);
    }
    __syncthreads();
    if (half){
        if (tid == 0){
            __threadfence();
            atomicAdd(&g_mpf[b], 1);
        }
        __syncthreads();
        return;
    }
    if (tid == 0) spinflag(&g_mpf[b], c);
    __syncthreads();
    if (tid < MELN) ls[tid] = __ldcg(&g_mls[b*132 + tid]);
    __syncthreads();
    red[tid] = (tid < MELN) ? ls[tid] : -3.4e38f;
    __syncthreads();
    for (int off = 256; off > 0; off >>= 1){
        if (tid < off) red[tid] = fmaxf(red[tid], red[tid + off]);
        __syncthreads();
    }
    float m = red[0];
    __syncthreads();
    red[tid] = (tid < MELN) ? expf(ls[tid] - m) : 0.f;
    __syncthreads();
    for (int off = 256; off > 0; off >>= 1){
        if (tid < off) red[tid] += red[tid + off];
        __syncthreads();
    }
    float z = m + logf(red[0]);
    if (tid < MELN)
        outmel[((size_t)b*TT + t)*MELN + tid] = ls[tid] - z;
    if (tid == 0){
        int ix = 0; float bv = ls[0];
        for (int cc = 1; cc < MELN; cc++) if (ls[cc] > bv){ bv = ls[cc]; ix = cc; }
        midx[b] = ix;
        __threadfence();
        atomicAdd(&g_mfl, 1);
    }
    __syncthreads();
}

__device__ __forceinline__ void gi1t_body(const float* __restrict__ cond,
                                          const float* __restrict__ w_ih1)
{
    int id = blockIdx.x*512 + threadIdx.x;
#pragma unroll 1
    for (int r = 0; r < 3; r++){
        int id2 = id + r*65536;
        int t = id2 / G3;
        int n = id2 - t*G3;
        float wr[RHYN], wc[CHN];
#pragma unroll
        for (int j = 0; j < RHYN; j++) wr[j] = __ldg(w_ih1 + (size_t)n*273 + MELN + j);
#pragma unroll
        for (int j = 0; j < CHN; j++)
            wc[j] = __ldg(w_ih1 + (size_t)n*273 + MELN + RHYN + 128 + j);
#pragma unroll 1
        for (int b = 0; b < NB; b++){
            float s = g_gi1z[(size_t)b*G3 + n];
            const float* rl = g_rlo + (t*NB + b)*RHYN;
            s += __ldcg(rl)*wr[0] + __ldcg(rl+1)*wr[1] + __ldcg(rl+2)*wr[2];
            const float* c = cond + ((size_t)b*TT + t)*CHN;
#pragma unroll
            for (int j = 0; j < CHN; j++) s += __ldg(c + j)*wc[j];
            g_gi1t[((size_t)t*NB + b)*G3 + n] = s;
        }
    }
}

// ---------------- persistent main kernel ------------------------------------------
__global__ __launch_bounds__(512, 1) void k_main(
    const float* __restrict__ w_ih0, const float* __restrict__ b_hh0,
    const float* __restrict__ w_ih1, const float* __restrict__ b_hh1,
    const float* __restrict__ b_ih2, const float* __restrict__ b_hh2,
    const float* __restrict__ wo0, const float* __restrict__ bo0,
    const float* __restrict__ wo1, const float* __restrict__ bo1,
    const float* __restrict__ cond, float* __restrict__ out,
    const float* __restrict__ z1, const float* __restrict__ z2,
    const float* __restrict__ wi0, const float* __restrict__ bi0,
    const float* __restrict__ wi1, const float* __restrict__ bi1,
    const float* __restrict__ b_ih0, const float* __restrict__ b_ih1,
    const float* __restrict__ w_hh0, const float* __restrict__ w_hh1,
    const float* __restrict__ w_ih2, const float* __restrict__ w_hh2)
{
    __shared__ float pool[9216];
    int tgt = 0;
    int tid = threadIdx.x, bid = blockIdx.x;
    float acc[2][3][4];

    // ================= phase 0: precompute (mv jobs + weight pack) =================
    {
        const float *zsrc, *W, *bias;
        int ldw, off, isH, nbase;
        float* dsth = 0; uint32_t* dstf = 0; float* dstg = 0;
        if (bid < 16){ zsrc=z2; W=wi0; bias=bi0; ldw=128; off=0; isH=1;
                       dsth=g_h; dstf=g_hfrag[0]; nbase=bid*128; }
        else if (bid < 32){ zsrc=z1; W=wi1; bias=bi1; ldw=128; off=0; isH=1;
                       dsth=g_ha; dstf=g_hafrag[0]; nbase=(bid-16)*128; }
        else if (bid < 80){ zsrc=z2; W=w_ih0; bias=b_ih0; ldw=131; off=RHYN; isH=0;
                       dstg=g_gic0; nbase=(bid-32)*128; }
        else { zsrc=z1; W=w_ih1; bias=b_ih1; ldw=273; off=MELN+RHYN; isH=0;
                       dstg=g_gi1z; nbase=(bid-80)*128; }
        for (int i = tid; i < 8192; i += 512)
            pool[(i & 127)*64 + (i >> 7)] = __ldg(zsrc + (i >> 7)*128 + (i & 127));
        __syncthreads();
        int np = tid >> 3, bg = tid & 7;
        int n0 = nbase + np*2;
        const float* w0 = W + (size_t)n0*ldw + off;
        const float* w1 = w0 + ldw;
        float a0[8], a1[8];
#pragma unroll
        for (int j = 0; j < 8; j++){ a0[j] = 0.f; a1[j] = 0.f; }
        for (int k = 0; k < 128; k++){
            float u = __ldg(w0 + k), v = __ldg(w1 + k);
            const float* zp = pool + k*64 + bg*8;
#pragma unroll
            for (int j = 0; j < 8; j++){
                float xv = zp[j];
                a0[j] += xv*u; a1[j] += xv*v;
            }
        }
        float b0v = __ldg(bias + n0), b1v = __ldg(bias + n0 + 1);
#pragma unroll
        for (int j = 0; j < 8; j++){
            int b = bg*8 + j;
            float v0 = a0[j] + b0v, v1 = a1[j] + b1v;
            if (isH){
                v0 = tanh_f(v0); v1 = tanh_f(v1);
                *(float2*)&dsth[(size_t)b*Hd + n0] = make_float2(v0, v1);
                frag_write(dstf, b, n0, v0, v1);
            } else {
                *(float2*)&dstg[(size_t)b*G3 + n0] = make_float2(v0, v1);
            }
        }
        __syncthreads();
        const float* Ws[4] = { w_hh0, w_hh1, w_ih2, w_hh2 };
        uint4* Os[4] = { g_Bp0, g_Bp1, g_Bp2i, g_Bp2h };
#pragma unroll 1
        for (int mat = 0; mat < 4; mat++){
            const float* W4 = Ws[mat];
            uint4* o4 = Os[mat];
#pragma unroll 1
            for (int it = 0; it < 48; it++){
                int id = (bid*512 + tid) + it*65536;
                int l = id & 31, nt = id >> 12;
                int P = nt*8 + (l >> 2);
                int jt = P/48, rem = P%48, g = rem >> 4, c = rem & 15;
                int k16 = (id >> 5) & 127;
                const float* wr = W4 + (size_t)(g*Hd + jt*16 + c)*Hd + k16*16 + 2*(l&3);
                uint4 vv;
                split2(__ldg(wr), __ldg(wr+1), vv.x, vv.z);
                split2(__ldg(wr+8), __ldg(wr+9), vv.y, vv.w);
                o4[id] = vv;
            }
        }
        gbar(tgt);
    }

    // ================= rhythm phase (1 barrier/step) ===============================
#pragma unroll 1
    for (int t = 0; t < TT; t++){
        int cu = t & 1, nx = cu ^ 1;
        if (t > 0)
            rhy_body(g_h + (size_t)cu*NBHd, wo0, bo0,
                     g_rlo + (t-1)*NB*RHYN, g_ridx + t*NB, pool, t);
        gemm_acc(g_Bp0, g_hfrag[cu], acc, pool);
        if (tid == 0) spinflag(&g_rfl, 64*t);
        __syncthreads();
        if (tid < 128)
            epiA(acc, b_hh0, g_gic0, w_ih0, 131, g_ridx + t*NB,
                 g_h + (size_t)cu*NBHd, g_h + (size_t)nx*NBHd, g_hfrag[nx]);
        gbar(tgt);
    }
    rhy_body(g_h + (size_t)0*NBHd, wo0, bo0,
             g_rlo + 31*NB*RHYN, g_ridx + 32*NB, pool, 32);
    gbar(tgt);
    gi1t_body(cond, w_ih1);
    gbar(tgt);

    // ================= melody phase (2 barriers/step) ==============================
#pragma unroll 1
    for (int t = 0; t < TT; t++){
        int cu = t & 1, nx = cu ^ 1;
        if (t > 0)
            mel_body(g_hb + (size_t)cu*NBHd, wo1, bo1, out, t-1,
                     g_midx + t*NB, pool, t);
        gemm_acc(g_Bp1, g_hafrag[cu], acc, pool);
        if (tid == 0) spinflag(&g_mfl, 64*t);
        __syncthreads();
        if (tid < 128)
            epiA(acc, b_hh1, g_gi1t + (size_t)t*NB*G3, w_ih1, 273, g_midx + t*NB,
                 g_ha + (size_t)cu*NBHd, g_ha + (size_t)nx*NBHd, g_hafrag[nx]);
        gbar(tgt);
        const uint32_t* fbin = (t == 0) ? g_hafrag[1] : g_hbfrag[cu];
        const float* hbprev = (t == 0) ? (g_ha + (size_t)NBHd) : (g_hb + (size_t)cu*NBHd);
        gemm_acc(g_Bp2h, fbin, acc, pool);
        float gh2[2][3][4];
        if (tid < 128){
#pragma unroll
            for (int n = 0; n < 2; n++)
#pragma unroll
                for (int g = 0; g < 3; g++)
#pragma unroll
                    for (int i = 0; i < 4; i++) gh2[n][g][i] = acc[n][g][i];
        }
        gemm_acc(g_Bp2i, g_hafrag[nx], acc, pool);
        if (tid < 128)
            epi2(acc, gh2, b_ih2, b_hh2, hbprev,
                 g_hb + (size_t)nx*NBHd, g_hbfrag[nx]);
        gbar(tgt);
    }
    mel_body(g_hb + (size_t)0*NBHd, wo1, bo1, out, 31, g_midx + 32*NB, pool, 32);
}

// ---------------- host driver ------------------------------------------------------
extern "C" void kernel_launch(void* const* d_in, const int* in_sizes, int n_in,
                              void* d_out, int out_size)
{
    const float* z1    = (const float*)d_in[0];
    const float* z2    = (const float*)d_in[1];
    const float* cond  = (const float*)d_in[2];
    const float* w_ih0 = (const float*)d_in[3];
    const float* w_hh0 = (const float*)d_in[4];
    const float* b_ih0 = (const float*)d_in[5];
    const float* b_hh0 = (const float*)d_in[6];
    const float* w_ih1 = (const float*)d_in[7];
    const float* w_hh1 = (const float*)d_in[8];
    const float* b_ih1 = (const float*)d_in[9];
    const float* b_hh1 = (const float*)d_in[10];
    const float* w_ih2 = (const float*)d_in[11];
    const float* w_hh2 = (const float*)d_in[12];
    const float* b_ih2 = (const float*)d_in[13];
    const float* b_hh2 = (const float*)d_in[14];
    const float* wi0   = (const float*)d_in[15];
    const float* bi0   = (const float*)d_in[16];
    const float* wo0   = (const float*)d_in[17];
    const float* bo0   = (const float*)d_in[18];
    const float* wi1   = (const float*)d_in[19];
    const float* bi1   = (const float*)d_in[20];
    const float* wo1   = (const float*)d_in[21];
    const float* bo1   = (const float*)d_in[22];
    float* out = (float*)d_out;

    k_init<<<1, 64>>>();
    k_main<<<128, 512>>>(w_ih0, b_hh0, w_ih1, b_hh1, b_ih2, b_hh2,
                         wo0, bo0, wo1, bo1, cond, out,
                         z1, z2, wi0, bi0, wi1, bi1, b_ih0, b_ih1,
                         w_hh0, w_hh1, w_ih2, w_hh2);
}